// round 1
// baseline (speedup 1.0000x reference)
#include <cuda_runtime.h>
#include <math.h>

#define NTOK 2304
#define HWDIM 48
#define FEATC 256
#define NHEAD 8
#define DKV 32

// Scratch: pe(30*2304) + biasQ/biasK(2*256*2304) + Q,K,V,O,O2,H1,PRE (7*4*256*2304)
__device__ float g_scratch[17763840];
__device__ float g_scale[256];
__device__ float g_shift[256];

// ---------------- PE ----------------
__global__ void pe_kernel(float* __restrict__ pe) {
    int idx = blockIdx.x * blockDim.x + threadIdx.x;
    if (idx >= 30 * NTOK) return;
    int c = idx / NTOK, p = idx % NTOK;
    int i = p / HWDIM, j = p % HWDIM;
    const float SC = 6.283185307179586f;
    int axis = c / 10, t = c % 10;
    float e;
    if (axis == 0)      e = (float)(i + 1) / (HWDIM + 1e-6f) * SC;
    else if (axis == 1) e = (float)(j + 1) / (HWDIM + 1e-6f) * SC;
    else                e = SC;
    float freq = powf(10000.0f, (2.0f * (float)(t >> 1)) / 10.0f);
    float ph = e / freq;
    pe[idx] = (t & 1) ? cosf(ph) : sinf(ph);
}

// ---------------- PE bias matrices: biasQ/K[c][p] = sum_j w[c][256+j]*pe[j][p] ----------------
__global__ void pebias_kernel(const float* __restrict__ pe,
                              const float* __restrict__ wq,
                              const float* __restrict__ wk,
                              float* __restrict__ bq,
                              float* __restrict__ bk) {
    int p = blockIdx.x * blockDim.x + threadIdx.x;  // 0..2303
    int c = blockIdx.y;                              // 0..255
    const float* w = (blockIdx.z == 0 ? wq : wk) + (size_t)c * 286 + 256;
    float* o = (blockIdx.z == 0 ? bq : bk);
    float s = 0.f;
#pragma unroll
    for (int j = 0; j < 30; j++) s += w[j] * pe[j * NTOK + p];
    o[(size_t)c * NTOK + p] = s;
}

// ---------------- SGEMM: out[256 x 2304] = W[256 x 256](ldw) @ X[256 x 2304] + epilogue ----------------
__global__ void gemm_kernel(const float* __restrict__ W, int ldw,
                            const float* __restrict__ X,
                            const float* __restrict__ bMat,
                            const float* __restrict__ bVec,
                            const float* __restrict__ resid,
                            float* __restrict__ out, int relu) {
    __shared__ float As[16][68];  // pad 68: conflict-light writes, 16B-aligned rows
    __shared__ float Bs[16][64];
    int tid = threadIdx.x;
    int ty = tid >> 4, tx = tid & 15;
    int row0 = blockIdx.y * 64, col0 = blockIdx.x * 64;
    float acc[4][4];
#pragma unroll
    for (int i = 0; i < 4; i++)
#pragma unroll
        for (int j = 0; j < 4; j++) acc[i][j] = 0.f;

    for (int k0 = 0; k0 < 256; k0 += 16) {
#pragma unroll
        for (int i = 0; i < 4; i++) {
            int idx = tid + i * 256;
            int kk = idx & 15, mm = idx >> 4;
            As[kk][mm] = W[(size_t)(row0 + mm) * ldw + k0 + kk];
        }
#pragma unroll
        for (int i = 0; i < 4; i++) {
            int idx = tid + i * 256;
            int nn = idx & 63, kk = idx >> 6;
            Bs[kk][nn] = X[(size_t)(k0 + kk) * NTOK + col0 + nn];
        }
        __syncthreads();
#pragma unroll
        for (int kk = 0; kk < 16; kk++) {
            float4 a4 = *(const float4*)&As[kk][ty * 4];
            float4 b4 = *(const float4*)&Bs[kk][tx * 4];
            float a[4] = {a4.x, a4.y, a4.z, a4.w};
            float b[4] = {b4.x, b4.y, b4.z, b4.w};
#pragma unroll
            for (int i = 0; i < 4; i++)
#pragma unroll
                for (int j = 0; j < 4; j++) acc[i][j] += a[i] * b[j];
        }
        __syncthreads();
    }

#pragma unroll
    for (int i = 0; i < 4; i++) {
        int r = row0 + ty * 4 + i;
#pragma unroll
        for (int j = 0; j < 4; j++) {
            int c = col0 + tx * 4 + j;
            size_t o = (size_t)r * NTOK + c;
            float v = acc[i][j];
            if (bMat)  v += bMat[o];
            if (bVec)  v += bVec[r];
            if (relu)  v = fmaxf(v, 0.f);
            if (resid) v += resid[o];
            out[o] = v;
        }
    }
}

// ---------------- Flash attention: per (b,h), N=2304 tokens, d=32 ----------------
__global__ void attn_kernel(const float* __restrict__ Q,
                            const float* __restrict__ K,
                            const float* __restrict__ V,
                            float* __restrict__ O) {
    int bh = blockIdx.y;
    int b = bh >> 3, h = bh & 7;
    size_t head_off = ((size_t)b * FEATC + h * DKV) * NTOK;
    const float* Qp = Q + head_off;
    const float* Kp = K + head_off;
    const float* Vp = V + head_off;
    float* Op = O + head_off;

    int qi = blockIdx.x * 128 + threadIdx.x;

    float qv[32];
#pragma unroll
    for (int d = 0; d < 32; d++)
        qv[d] = Qp[(size_t)d * NTOK + qi] * 0.17677669529663687f;  // 1/sqrt(32)

    float m = -1e30f, l = 0.f;
    float acc[32];
#pragma unroll
    for (int d = 0; d < 32; d++) acc[d] = 0.f;

    __shared__ float Ks[64][36];  // pad 36: 16B-aligned rows, broadcast reads
    __shared__ float Vs[64][36];

    for (int kb = 0; kb < NTOK; kb += 64) {
        __syncthreads();
#pragma unroll
        for (int i = 0; i < 16; i++) {
            int idx = threadIdx.x + i * 128;
            int d = idx >> 6, j = idx & 63;
            Ks[j][d] = Kp[(size_t)d * NTOK + kb + j];
            Vs[j][d] = Vp[(size_t)d * NTOK + kb + j];
        }
        __syncthreads();

#pragma unroll 1
        for (int c0 = 0; c0 < 64; c0 += 8) {
            float s[8];
#pragma unroll
            for (int jj = 0; jj < 8; jj++) {
                const float4* kr = (const float4*)&Ks[c0 + jj][0];
                float sv = 0.f;
#pragma unroll
                for (int d4 = 0; d4 < 8; d4++) {
                    float4 kk = kr[d4];
                    sv += qv[4 * d4 + 0] * kk.x;
                    sv += qv[4 * d4 + 1] * kk.y;
                    sv += qv[4 * d4 + 2] * kk.z;
                    sv += qv[4 * d4 + 3] * kk.w;
                }
                s[jj] = sv;
            }
            float cmax = s[0];
#pragma unroll
            for (int jj = 1; jj < 8; jj++) cmax = fmaxf(cmax, s[jj]);
            if (cmax > m) {
                float corr = __expf(m - cmax);
                l *= corr;
#pragma unroll
                for (int d = 0; d < 32; d++) acc[d] *= corr;
                m = cmax;
            }
#pragma unroll
            for (int jj = 0; jj < 8; jj++) {
                float p = __expf(s[jj] - m);
                l += p;
                const float4* vr = (const float4*)&Vs[c0 + jj][0];
#pragma unroll
                for (int d4 = 0; d4 < 8; d4++) {
                    float4 vv = vr[d4];
                    acc[4 * d4 + 0] += p * vv.x;
                    acc[4 * d4 + 1] += p * vv.y;
                    acc[4 * d4 + 2] += p * vv.z;
                    acc[4 * d4 + 3] += p * vv.w;
                }
            }
        }
    }
    float inv = 1.f / l;
#pragma unroll
    for (int d = 0; d < 32; d++)
        Op[(size_t)d * NTOK + qi] = acc[d] * inv;
}

// ---------------- BN stats: one block per channel ----------------
__global__ void bnstats_kernel(const float* __restrict__ pre,
                               const float* __restrict__ gamma,
                               const float* __restrict__ beta) {
    int c = blockIdx.x;
    float s = 0.f, s2 = 0.f;
    for (int b = 0; b < 4; b++) {
        const float* p = pre + ((size_t)b * FEATC + c) * NTOK;
        for (int i = threadIdx.x; i < NTOK; i += 256) {
            float v = p[i];
            s += v;
            s2 += v * v;
        }
    }
    __shared__ float sh0[256], sh1[256];
    sh0[threadIdx.x] = s;
    sh1[threadIdx.x] = s2;
    __syncthreads();
    for (int st = 128; st > 0; st >>= 1) {
        if (threadIdx.x < st) {
            sh0[threadIdx.x] += sh0[threadIdx.x + st];
            sh1[threadIdx.x] += sh1[threadIdx.x + st];
        }
        __syncthreads();
    }
    if (threadIdx.x == 0) {
        const float n = 4.0f * NTOK;
        float mean = sh0[0] / n;
        float var = sh1[0] / n - mean * mean;
        float is = rsqrtf(var + 1e-5f);
        float sc = gamma[c] * is;
        g_scale[c] = sc;
        g_shift[c] = beta[c] - mean * sc;
    }
}

__global__ void bnapply_kernel(const float* __restrict__ pre, float* __restrict__ out) {
    int idx = blockIdx.x * 256 + threadIdx.x;
    if (idx >= 4 * FEATC * NTOK) return;
    int c = (idx / NTOK) & 255;
    out[idx] = pre[idx] * g_scale[c] + g_shift[c];
}

// ---------------- launch ----------------
extern "C" void kernel_launch(void* const* d_in, const int* in_sizes, int n_in,
                              void* d_out, int out_size) {
    const float* q     = (const float*)d_in[0];
    const float* k     = (const float*)d_in[1];
    const float* v     = (const float*)d_in[2];
    const float* wq    = (const float*)d_in[3];
    const float* wk    = (const float*)d_in[4];
    const float* wv    = (const float*)d_in[5];
    const float* wfc   = (const float*)d_in[6];
    const float* w1    = (const float*)d_in[7];
    const float* b1    = (const float*)d_in[8];
    const float* w2    = (const float*)d_in[9];
    const float* b2    = (const float*)d_in[10];
    const float* gamma = (const float*)d_in[11];
    const float* beta  = (const float*)d_in[12];
    float* out = (float*)d_out;

    float* base = nullptr;
    cudaGetSymbolAddress((void**)&base, g_scratch);
    float* pe  = base;
    float* bq  = base + 69120;
    float* bk  = bq + 589824;
    float* Q   = bk + 589824;
    float* K   = Q + 2359296;
    float* V   = K + 2359296;
    float* O   = V + 2359296;
    float* O2  = O + 2359296;
    float* H1  = O2 + 2359296;
    float* PRE = H1 + 2359296;

    pe_kernel<<<(30 * NTOK + 255) / 256, 256>>>(pe);
    {
        dim3 g(NTOK / 128, 256, 2);
        pebias_kernel<<<g, 128>>>(pe, wq, wk, bq, bk);
    }
    dim3 gg(NTOK / 64, FEATC / 64);
    for (int b = 0; b < 4; b++) {
        size_t off = (size_t)b * FEATC * NTOK;
        gemm_kernel<<<gg, 256>>>(wq, 286, q + off, bq, nullptr, nullptr, Q + off, 0);
        gemm_kernel<<<gg, 256>>>(wk, 286, k + off, bk, nullptr, nullptr, K + off, 0);
        gemm_kernel<<<gg, 256>>>(wv, 256, v + off, nullptr, nullptr, nullptr, V + off, 0);
    }
    {
        dim3 ga(NTOK / 128, 32);
        attn_kernel<<<ga, 128>>>(Q, K, V, O);
    }
    for (int b = 0; b < 4; b++) {
        size_t off = (size_t)b * FEATC * NTOK;
        gemm_kernel<<<gg, 256>>>(wfc, 256, O + off, nullptr, nullptr, nullptr, O2 + off, 0);
    }
    for (int b = 0; b < 4; b++) {
        size_t off = (size_t)b * FEATC * NTOK;
        gemm_kernel<<<gg, 256>>>(w1, 256, O2 + off, nullptr, b1, nullptr, H1 + off, 1);
    }
    for (int b = 0; b < 4; b++) {
        size_t off = (size_t)b * FEATC * NTOK;
        gemm_kernel<<<gg, 256>>>(w2, 256, H1 + off, nullptr, b2, O2 + off, PRE + off, 0);
    }
    bnstats_kernel<<<256, 256>>>(PRE, gamma, beta);
    bnapply_kernel<<<(4 * FEATC * NTOK + 255) / 256, 256>>>(PRE, out);
}

// round 2
// speedup vs baseline: 1.3721x; 1.3721x over previous
#include <cuda_runtime.h>
#include <math.h>

#define NTOK 2304
#define HWDIM 48
#define FEATC 256
#define NHEAD 8
#define DKV 32

typedef unsigned long long ull;

// Scratch: pe(30*2304) + biasQ/biasK(2*256*2304) + Q,K,V,O,O2,H1,PRE (7*4*256*2304)
__device__ float g_scratch[17763840];
__device__ float g_scale[256];
__device__ float g_shift[256];

// ---- f32x2 helpers ----
__device__ __forceinline__ ull pk(float lo, float hi) {
    ull r; asm("mov.b64 %0,{%1,%2};" : "=l"(r) : "f"(lo), "f"(hi)); return r;
}
__device__ __forceinline__ void fma2(ull& d, ull a, ull b) {
    asm("fma.rn.f32x2 %0,%1,%2,%0;" : "+l"(d) : "l"(a), "l"(b));
}
__device__ __forceinline__ ull mul2(ull a, ull b) {
    ull r; asm("mul.rn.f32x2 %0,%1,%2;" : "=l"(r) : "l"(a), "l"(b)); return r;
}
__device__ __forceinline__ float plo(ull u) { return __uint_as_float((unsigned)u); }
__device__ __forceinline__ float phi(ull u) { return __uint_as_float((unsigned)(u >> 32)); }

// ---------------- PE ----------------
__global__ void pe_kernel(float* __restrict__ pe) {
    int idx = blockIdx.x * blockDim.x + threadIdx.x;
    if (idx >= 30 * NTOK) return;
    int c = idx / NTOK, p = idx % NTOK;
    int i = p / HWDIM, j = p % HWDIM;
    const float SC = 6.283185307179586f;
    int axis = c / 10, t = c % 10;
    float e;
    if (axis == 0)      e = (float)(i + 1) / (HWDIM + 1e-6f) * SC;
    else if (axis == 1) e = (float)(j + 1) / (HWDIM + 1e-6f) * SC;
    else                e = SC;
    float freq = powf(10000.0f, (2.0f * (float)(t >> 1)) / 10.0f);
    float ph = e / freq;
    pe[idx] = (t & 1) ? cosf(ph) : sinf(ph);
}

// ---------------- PE bias ----------------
__global__ void pebias_kernel(const float* __restrict__ pe,
                              const float* __restrict__ wq,
                              const float* __restrict__ wk,
                              float* __restrict__ bq,
                              float* __restrict__ bk) {
    int p = blockIdx.x * blockDim.x + threadIdx.x;
    int c = blockIdx.y;
    const float* w = (blockIdx.z == 0 ? wq : wk) + (size_t)c * 286 + 256;
    float* o = (blockIdx.z == 0 ? bq : bk);
    float s = 0.f;
#pragma unroll
    for (int j = 0; j < 30; j++) s += w[j] * pe[j * NTOK + p];
    o[(size_t)c * NTOK + p] = s;
}

// ---------------- SGEMM body: out[256 x 2304] = W @ X + epilogue ----------------
__device__ __forceinline__ void gemm_body(const float* __restrict__ W, int ldw,
                                          const float* __restrict__ X,
                                          const float* __restrict__ bMat,
                                          const float* __restrict__ bVec,
                                          const float* __restrict__ resid,
                                          float* __restrict__ out, int relu) {
    __shared__ float As[16][68];
    __shared__ float Bs[16][64];
    int tid = threadIdx.x;
    int ty = tid >> 4, tx = tid & 15;
    int row0 = blockIdx.y * 64, col0 = blockIdx.x * 64;
    float acc[4][4];
#pragma unroll
    for (int i = 0; i < 4; i++)
#pragma unroll
        for (int j = 0; j < 4; j++) acc[i][j] = 0.f;

    for (int k0 = 0; k0 < 256; k0 += 16) {
#pragma unroll
        for (int i = 0; i < 4; i++) {
            int idx = tid + i * 256;
            int kk = idx & 15, mm = idx >> 4;
            As[kk][mm] = W[(size_t)(row0 + mm) * ldw + k0 + kk];
        }
#pragma unroll
        for (int i = 0; i < 4; i++) {
            int idx = tid + i * 256;
            int nn = idx & 63, kk = idx >> 6;
            Bs[kk][nn] = X[(size_t)(k0 + kk) * NTOK + col0 + nn];
        }
        __syncthreads();
#pragma unroll
        for (int kk = 0; kk < 16; kk++) {
            float4 a4 = *(const float4*)&As[kk][ty * 4];
            float4 b4 = *(const float4*)&Bs[kk][tx * 4];
            float a[4] = {a4.x, a4.y, a4.z, a4.w};
            float b[4] = {b4.x, b4.y, b4.z, b4.w};
#pragma unroll
            for (int i = 0; i < 4; i++)
#pragma unroll
                for (int j = 0; j < 4; j++) acc[i][j] += a[i] * b[j];
        }
        __syncthreads();
    }

#pragma unroll
    for (int i = 0; i < 4; i++) {
        int r = row0 + ty * 4 + i;
#pragma unroll
        for (int j = 0; j < 4; j++) {
            int c = col0 + tx * 4 + j;
            size_t o = (size_t)r * NTOK + c;
            float v = acc[i][j];
            if (bMat)  v += bMat[o];
            if (bVec)  v += bVec[r];
            if (relu)  v = fmaxf(v, 0.f);
            if (resid) v += resid[o];
            out[o] = v;
        }
    }
}

// Fused QKV projections: z = batch*3 + op
__global__ void proj_kernel(const float* __restrict__ wq, const float* __restrict__ wk,
                            const float* __restrict__ wv,
                            const float* __restrict__ q, const float* __restrict__ k,
                            const float* __restrict__ v,
                            const float* __restrict__ bq, const float* __restrict__ bk,
                            float* __restrict__ Q, float* __restrict__ K, float* __restrict__ V) {
    int z = blockIdx.z;
    int b = z / 3, op = z - 3 * b;
    size_t off = (size_t)b * FEATC * NTOK;
    const float* W;
    const float* X;
    const float* bMat;
    float* out;
    int ldw;
    if (op == 0)      { W = wq; ldw = 286; X = q + off; bMat = bq; out = Q + off; }
    else if (op == 1) { W = wk; ldw = 286; X = k + off; bMat = bk; out = K + off; }
    else              { W = wv; ldw = 256; X = v + off; bMat = nullptr; out = V + off; }
    gemm_body(W, ldw, X, bMat, nullptr, nullptr, out, 0);
}

// Batched generic GEMM: z = batch
__global__ void gemm_kernel(const float* __restrict__ W, int ldw,
                            const float* __restrict__ X,
                            const float* __restrict__ bVec,
                            const float* __restrict__ resid,
                            float* __restrict__ out, int relu) {
    size_t off = (size_t)blockIdx.z * FEATC * NTOK;
    gemm_body(W, ldw, X + off, nullptr, bVec, resid ? resid + off : nullptr, out + off, relu);
}

// ---------------- Flash attention, f32x2, 2 queries/thread ----------------
__global__ void __launch_bounds__(128) attn_kernel(const float* __restrict__ Q,
                                                   const float* __restrict__ K,
                                                   const float* __restrict__ V,
                                                   float* __restrict__ O) {
    int bh = blockIdx.y;
    int b = bh >> 3, h = bh & 7;
    size_t head_off = ((size_t)b * FEATC + h * DKV) * NTOK;
    const float* Qp = Q + head_off;
    const float* Kp = K + head_off;
    const float* Vp = V + head_off;
    float* Op = O + head_off;

    int q0 = blockIdx.x * 256 + threadIdx.x;
    int q1 = q0 + 128;

    const float sc = 0.17677669529663687f;  // 1/sqrt(32)
    ull qp0[16], qp1[16];
#pragma unroll
    for (int d2 = 0; d2 < 16; d2++) {
        qp0[d2] = pk(Qp[(size_t)(2 * d2) * NTOK + q0] * sc, Qp[(size_t)(2 * d2 + 1) * NTOK + q0] * sc);
        qp1[d2] = pk(Qp[(size_t)(2 * d2) * NTOK + q1] * sc, Qp[(size_t)(2 * d2 + 1) * NTOK + q1] * sc);
    }

    float m0 = -1e30f, l0 = 0.f, m1 = -1e30f, l1 = 0.f;
    ull acc0[16], acc1[16];
#pragma unroll
    for (int d2 = 0; d2 < 16; d2++) { acc0[d2] = 0ull; acc1[d2] = 0ull; }

    __shared__ float Ks[64][36];
    __shared__ float Vs[64][36];

    for (int kb = 0; kb < NTOK; kb += 64) {
        __syncthreads();
#pragma unroll
        for (int i = 0; i < 16; i++) {
            int idx = threadIdx.x + i * 128;
            int d = idx >> 6, j = idx & 63;
            Ks[j][d] = Kp[(size_t)d * NTOK + kb + j];
            Vs[j][d] = Vp[(size_t)d * NTOK + kb + j];
        }
        __syncthreads();

#pragma unroll 1
        for (int c0 = 0; c0 < 64; c0 += 8) {
            float s0[8], s1[8];
#pragma unroll
            for (int jj = 0; jj < 8; jj++) {
                const ulonglong2* kr = (const ulonglong2*)&Ks[c0 + jj][0];
                ull sp0 = 0ull, sp1 = 0ull;
#pragma unroll
                for (int i = 0; i < 8; i++) {
                    ulonglong2 kk = kr[i];
                    fma2(sp0, qp0[2 * i], kk.x);
                    fma2(sp0, qp0[2 * i + 1], kk.y);
                    fma2(sp1, qp1[2 * i], kk.x);
                    fma2(sp1, qp1[2 * i + 1], kk.y);
                }
                s0[jj] = plo(sp0) + phi(sp0);
                s1[jj] = plo(sp1) + phi(sp1);
            }
            float c0m = s0[0], c1m = s1[0];
#pragma unroll
            for (int jj = 1; jj < 8; jj++) { c0m = fmaxf(c0m, s0[jj]); c1m = fmaxf(c1m, s1[jj]); }
            if (c0m > m0) {
                float corr = __expf(m0 - c0m);
                l0 *= corr;
                ull cd = pk(corr, corr);
#pragma unroll
                for (int d2 = 0; d2 < 16; d2++) acc0[d2] = mul2(acc0[d2], cd);
                m0 = c0m;
            }
            if (c1m > m1) {
                float corr = __expf(m1 - c1m);
                l1 *= corr;
                ull cd = pk(corr, corr);
#pragma unroll
                for (int d2 = 0; d2 < 16; d2++) acc1[d2] = mul2(acc1[d2], cd);
                m1 = c1m;
            }
#pragma unroll
            for (int jj = 0; jj < 8; jj++) {
                float p0 = __expf(s0[jj] - m0);
                float p1 = __expf(s1[jj] - m1);
                l0 += p0; l1 += p1;
                ull pd0 = pk(p0, p0);
                ull pd1 = pk(p1, p1);
                const ulonglong2* vr = (const ulonglong2*)&Vs[c0 + jj][0];
#pragma unroll
                for (int i = 0; i < 8; i++) {
                    ulonglong2 vv = vr[i];
                    fma2(acc0[2 * i], pd0, vv.x);
                    fma2(acc0[2 * i + 1], pd0, vv.y);
                    fma2(acc1[2 * i], pd1, vv.x);
                    fma2(acc1[2 * i + 1], pd1, vv.y);
                }
            }
        }
    }
    float inv0 = 1.f / l0, inv1 = 1.f / l1;
#pragma unroll
    for (int d2 = 0; d2 < 16; d2++) {
        Op[(size_t)(2 * d2) * NTOK + q0]     = plo(acc0[d2]) * inv0;
        Op[(size_t)(2 * d2 + 1) * NTOK + q0] = phi(acc0[d2]) * inv0;
        Op[(size_t)(2 * d2) * NTOK + q1]     = plo(acc1[d2]) * inv1;
        Op[(size_t)(2 * d2 + 1) * NTOK + q1] = phi(acc1[d2]) * inv1;
    }
}

// ---------------- BN ----------------
__global__ void bnstats_kernel(const float* __restrict__ pre,
                               const float* __restrict__ gamma,
                               const float* __restrict__ beta) {
    int c = blockIdx.x;
    float s = 0.f, s2 = 0.f;
    for (int b = 0; b < 4; b++) {
        const float* p = pre + ((size_t)b * FEATC + c) * NTOK;
        for (int i = threadIdx.x; i < NTOK; i += 256) {
            float v = p[i];
            s += v;
            s2 += v * v;
        }
    }
    __shared__ float sh0[256], sh1[256];
    sh0[threadIdx.x] = s;
    sh1[threadIdx.x] = s2;
    __syncthreads();
    for (int st = 128; st > 0; st >>= 1) {
        if (threadIdx.x < st) {
            sh0[threadIdx.x] += sh0[threadIdx.x + st];
            sh1[threadIdx.x] += sh1[threadIdx.x + st];
        }
        __syncthreads();
    }
    if (threadIdx.x == 0) {
        const float n = 4.0f * NTOK;
        float mean = sh0[0] / n;
        float var = sh1[0] / n - mean * mean;
        float is = rsqrtf(var + 1e-5f);
        float scl = gamma[c] * is;
        g_scale[c] = scl;
        g_shift[c] = beta[c] - mean * scl;
    }
}

__global__ void bnapply_kernel(const float* __restrict__ pre, float* __restrict__ out) {
    int idx = blockIdx.x * 256 + threadIdx.x;
    if (idx >= 4 * FEATC * NTOK) return;
    int c = (idx / NTOK) & 255;
    out[idx] = pre[idx] * g_scale[c] + g_shift[c];
}

// ---------------- launch ----------------
extern "C" void kernel_launch(void* const* d_in, const int* in_sizes, int n_in,
                              void* d_out, int out_size) {
    const float* q     = (const float*)d_in[0];
    const float* k     = (const float*)d_in[1];
    const float* v     = (const float*)d_in[2];
    const float* wq    = (const float*)d_in[3];
    const float* wk    = (const float*)d_in[4];
    const float* wv    = (const float*)d_in[5];
    const float* wfc   = (const float*)d_in[6];
    const float* w1    = (const float*)d_in[7];
    const float* b1    = (const float*)d_in[8];
    const float* w2    = (const float*)d_in[9];
    const float* b2    = (const float*)d_in[10];
    const float* gamma = (const float*)d_in[11];
    const float* beta  = (const float*)d_in[12];
    float* out = (float*)d_out;

    float* base = nullptr;
    cudaGetSymbolAddress((void**)&base, g_scratch);
    float* pe  = base;
    float* bq  = base + 69120;
    float* bk  = bq + 589824;
    float* Q   = bk + 589824;
    float* K   = Q + 2359296;
    float* V   = K + 2359296;
    float* O   = V + 2359296;
    float* O2  = O + 2359296;
    float* H1  = O2 + 2359296;
    float* PRE = H1 + 2359296;

    pe_kernel<<<(30 * NTOK + 255) / 256, 256>>>(pe);
    {
        dim3 g(NTOK / 128, 256, 2);
        pebias_kernel<<<g, 128>>>(pe, wq, wk, bq, bk);
    }
    {
        dim3 g(NTOK / 64, FEATC / 64, 12);
        proj_kernel<<<g, 256>>>(wq, wk, wv, q, k, v, bq, bk, Q, K, V);
    }
    {
        dim3 ga(NTOK / 256, 32);
        attn_kernel<<<ga, 128>>>(Q, K, V, O);
    }
    dim3 gg(NTOK / 64, FEATC / 64, 4);
    gemm_kernel<<<gg, 256>>>(wfc, 256, O, nullptr, nullptr, O2, 0);
    gemm_kernel<<<gg, 256>>>(w1, 256, O2, b1, nullptr, H1, 1);
    gemm_kernel<<<gg, 256>>>(w2, 256, H1, b2, O2, PRE, 0);
    bnstats_kernel<<<256, 256>>>(PRE, gamma, beta);
    bnapply_kernel<<<(4 * FEATC * NTOK + 255) / 256, 256>>>(PRE, out);
}